// round 15
// baseline (speedup 1.0000x reference)
#include <cuda_runtime.h>
#include <cuda_bf16.h>
#include <cstdint>

// Inputs (metadata order):
//   d_in[0] = x      float32 [262144]  (1 MB, random-gathered, L2-resident)
//   d_in[1] = A_vals float32 [NNZ]
//   d_in[2] = A_rows int32   [NNZ]
//   d_in[3] = A_cols int32   [NNZ]
// Output: float32 [262144]
//
// Unsorted-COO SpMV at the co-saturated L1tex/LTS floor (65.1us kernel, 512thr
// geometry optimum). R15: eliminate the init->spmv graph dependency. The SpMV
// accumulates into a statically zero-initialized __device__ scratch (invariant:
// zero on entry), so it is the FIRST graph node with no predecessor. A finalize
// kernel then publishes out = scratch and restores scratch = 0 for the next
// replay. Deterministic: identical work on every call.

#define THREADS 512
#define OUT_N   262144

__device__ float g_scratch[OUT_N];   // zero-initialized at module load

__global__ void __launch_bounds__(THREADS) coo_spmv_kernel(
    const float*  __restrict__ x,
    const float4* __restrict__ vals4,
    const int4*   __restrict__ rows4,
    const int4*   __restrict__ cols4,
    int nnz4)
{
    int i = blockIdx.x * blockDim.x + threadIdx.x;
    if (i >= nnz4) return;

    // Three independent 16B streaming loads -> MLP 3 per thread.
    float4 v = __ldg(&vals4[i]);
    int4   r = __ldg(&rows4[i]);
    int4   c = __ldg(&cols4[i]);

    // Random gathers from L2-resident x (1 MB).
    float x0 = __ldg(&x[c.x]);
    float x1 = __ldg(&x[c.y]);
    float x2 = __ldg(&x[c.z]);
    float x3 = __ldg(&x[c.w]);

    // Scatter-add into the zero-maintained scratch accumulator.
    atomicAdd(&g_scratch[r.x], v.x * x0);
    atomicAdd(&g_scratch[r.y], v.y * x1);
    atomicAdd(&g_scratch[r.z], v.z * x2);
    atomicAdd(&g_scratch[r.w], v.w * x3);
}

// Scalar tail accumulator (nnz % 4 != 0; unused for this shape).
__global__ void coo_spmv_tail_kernel(
    const float* __restrict__ x,
    const float* __restrict__ vals,
    const int*   __restrict__ rows,
    const int*   __restrict__ cols,
    int start, int nnz)
{
    int i = start + blockIdx.x * blockDim.x + threadIdx.x;
    if (i < nnz) {
        atomicAdd(&g_scratch[rows[i]], vals[i] * __ldg(&x[cols[i]]));
    }
}

// Publish result and restore the scratch-is-zero invariant for the next replay.
__global__ void finalize_kernel(float4* __restrict__ out, int n4) {
    int i = blockIdx.x * blockDim.x + threadIdx.x;
    if (i < n4) {
        float4* s4 = (float4*)g_scratch;
        out[i] = s4[i];
        s4[i] = make_float4(0.f, 0.f, 0.f, 0.f);
    }
}

extern "C" void kernel_launch(void* const* d_in, const int* in_sizes, int n_in,
                              void* d_out, int out_size) {
    const float* x    = (const float*)d_in[0];
    const float* vals = (const float*)d_in[1];
    const int*   rows = (const int*)d_in[2];
    const int*   cols = (const int*)d_in[3];
    float* out = (float*)d_out;

    const int nnz  = in_sizes[1];
    const int nnz4 = nnz / 4;

    // Node 1 (no predecessor): SpMV into zero-maintained scratch.
    if (nnz4 > 0) {
        int blocks = (nnz4 + THREADS - 1) / THREADS;   // 4096 for this shape
        coo_spmv_kernel<<<blocks, THREADS>>>(
            x, (const float4*)vals, (const int4*)rows, (const int4*)cols, nnz4);
    }

    // Tail (nnz % 4): empty for this shape -> no node enters the graph.
    int tail_start = nnz4 * 4;
    int tail = nnz - tail_start;
    if (tail > 0) {
        coo_spmv_tail_kernel<<<(tail + 255) / 256, 256>>>(
            x, vals, rows, cols, tail_start, nnz);
    }

    // Node 2: publish out, reset scratch (restores invariant for next replay).
    {
        int n4 = out_size / 4;               // out_size divisible by 4 here
        finalize_kernel<<<(n4 + THREADS - 1) / THREADS, THREADS>>>((float4*)out, n4);
    }
}